// round 5
// baseline (speedup 1.0000x reference)
#include <cuda_runtime.h>
#include <math.h>
#include <stdint.h>

// Problem constants
#define BB    256
#define FF    256
#define NJ3C  51
#define INDIM 34
#define DD    512
#define G4    2048
#define ROWW  1152          // unified state row stride (floats)
#define OFF_PRED 0          // [0,51)  pred, [51,64) zero pad
#define OFF_H0   64         // [64,576) h0
#define OFF_X    576        // [576,610) x, [610,624) zero pad
#define OFF_H1   624        // [624,1136) h1, rest pad
#define KA_PAD   624        // phase A K (incl zero pads)
#define NT_A     39         // 624/16
#define KB       1024
#define NT_B     64
#define NBLK     128

typedef unsigned long long ull;

// ---------------- device scratch (static, no allocation) ----------------
__device__ __align__(16) float d_buf[2][BB][ROWW];   // unified state, double buffered
__device__ __align__(16) float d_c0s[BB][DD];
__device__ __align__(16) float d_c1s[BB][DD];
__device__ __align__(16) float d_Wpk0[KA_PAD][G4];   // packed LSTM0 W, k-major, n=d*4+gate
__device__ float d_cb[G4];                           // folded bias LSTM0
__device__ __align__(16) float d_Wpk1[KB][G4];       // packed LSTM1 W
__device__ float d_b1g[G4];                          // bias LSTM1
__device__ __align__(16) float d_t1[BB][DD];
__device__ __align__(16) float d_t2[BB][1024];
__device__ __align__(16) float d_z[BB][G4];
__device__ unsigned d_bar_count;
__device__ volatile unsigned d_bar_gen;

__device__ __forceinline__ float sigm(float x){ return 1.0f/(1.0f+expf(-x)); }

// ---------------- packed f32x2 helpers (FFMA2 path) ----------------
#define PACK2(d, x) asm("mov.b64 %0, {%1, %1};" : "=l"(d) : "r"(__float_as_uint(x)))
#define FMA2(d, a, b) asm("fma.rn.f32x2 %0, %1, %2, %0;" : "+l"(d) : "l"(a), "l"(b))
__device__ __forceinline__ void unpack2(ull v, float& lo, float& hi){
  unsigned ulo, uhi;
  asm("mov.b64 {%0, %1}, %2;" : "=r"(ulo), "=r"(uhi) : "l"(v));
  lo = __uint_as_float(ulo); hi = __uint_as_float(uhi);
}

// ---------------- grid barrier (128 co-resident blocks) ----------------
__device__ __forceinline__ void grid_barrier(){
  __syncthreads();
  if (threadIdx.x == 0){
    unsigned gen = d_bar_gen;
    __threadfence();
    if (atomicAdd(&d_bar_count, 1u) == NBLK - 1){
      d_bar_count = 0;
      __threadfence();
      d_bar_gen = gen + 1;
    } else {
      while (d_bar_gen == gen) { __nanosleep(64); }
      __threadfence();
    }
  }
  __syncthreads();
}

// ---------------- 16-deep packed-FMA microtile core ----------------
__device__ __forceinline__ void mm16p(const float (*As)[68], const float (*Ws)[64],
                                      ull acc2[2][4], int m0, int n0){
#pragma unroll
  for (int kk = 0; kk < 16; kk++){
    ulonglong2 aa = *reinterpret_cast<const ulonglong2*>(&As[kk][m0]);
    float4 b4 = *reinterpret_cast<const float4*>(&Ws[kk][n0]);
    ull b0, b1, b2, b3;
    PACK2(b0, b4.x); PACK2(b1, b4.y); PACK2(b2, b4.z); PACK2(b3, b4.w);
    FMA2(acc2[0][0], aa.x, b0); FMA2(acc2[0][1], aa.x, b1);
    FMA2(acc2[0][2], aa.x, b2); FMA2(acc2[0][3], aa.x, b3);
    FMA2(acc2[1][0], aa.y, b0); FMA2(acc2[1][1], aa.y, b1);
    FMA2(acc2[1][2], aa.y, b2); FMA2(acc2[1][3], aa.y, b3);
  }
}

// ---------------- pack LSTM0 weights with pads + folded embedding ----------------
// k map: [0,51) Wih0 pred cols; [51,64) 0; [64,576) Whh0; [576,610) embed fold; [610,624) 0
__global__ void pack0_kernel(const float* __restrict__ Wih0, const float* __restrict__ Whh0,
                             const float* __restrict__ embW, const float* __restrict__ embB,
                             const float* __restrict__ bih0, const float* __restrict__ bhh0){
  int n = blockIdx.x;
  int j = (n & 3) * DD + (n >> 2);
  __shared__ float row[DD];
  for (int k = threadIdx.x; k < DD; k += 64) row[k] = Wih0[j*563 + k];
  __syncthreads();
  for (int k = threadIdx.x; k < KA_PAD; k += 64){
    float w;
    if (k < NJ3C)       w = Wih0[j*563 + DD + k];
    else if (k < 64)    w = 0.f;
    else if (k < 576)   w = Whh0[j*DD + (k - 64)];
    else if (k < 610){
      const float* er = embW + (k - 576)*DD;
      float s = 0.f;
      for (int kk = 0; kk < DD; kk++) s = fmaf(er[kk], row[kk], s);
      w = s;
    } else w = 0.f;
    d_Wpk0[k][n] = w;
  }
  if (threadIdx.x == 0){
    float s = 0.f;
    for (int kk = 0; kk < DD; kk++) s = fmaf(embB[kk], row[kk], s);
    d_cb[n] = s + bih0[j] + bhh0[j];
  }
}

__global__ void pack1_kernel(const float* __restrict__ Wih1, const float* __restrict__ Whh1,
                             const float* __restrict__ bih1, const float* __restrict__ bhh1){
  int idx = blockIdx.x * 256 + threadIdx.x;   // KB*G4
  int k = idx >> 11;
  int n = idx & (G4 - 1);
  int j = (n & 3) * DD + (n >> 2);
  d_Wpk1[k][n] = (k < DD) ? Wih1[j*DD + k] : Whh1[j*DD + (k - DD)];
  if (k == 0) d_b1g[n] = bih1[j] + bhh1[j];
}

// ---------------- init-MLP GEMM (one-shot) ----------------
__global__ __launch_bounds__(256)
void gemm_bias_act(const float* __restrict__ Aext, int a_sel, int lda,
                   const float* __restrict__ W, int N, int K,
                   const float* __restrict__ bias, int c_sel, int relu){
  const float* A = (a_sel == 0) ? Aext : (a_sel == 1 ? &d_t1[0][0] : &d_t2[0][0]);
  float* C = (c_sel == 1) ? &d_t1[0][0] : (c_sel == 2 ? &d_t2[0][0] : &d_z[0][0]);
  __shared__ __align__(16) float As[16][68];
  __shared__ __align__(16) float Ws[16][64];
  int tid = threadIdx.x;
  int tx = tid & 15, ty = tid >> 4;
  int nb = blockIdx.x * 64, mb = blockIdx.y * 64;
  int m0 = ty * 4, n0 = tx * 4;
  ull acc2[2][4];
#pragma unroll
  for (int j2 = 0; j2 < 4; j2++){
    float bv = bias[nb + n0 + j2];
    PACK2(acc2[0][j2], bv);
    acc2[1][j2] = acc2[0][j2];
  }
  int r  = tid >> 2, kq = (tid & 3) * 4;
  int wk = tid >> 4, wn = (tid & 15) * 4;
  for (int k0 = 0; k0 < K; k0 += 16){
#pragma unroll
    for (int i = 0; i < 4; i++){
      int k = k0 + kq + i;
      As[kq+i][r] = (k < K) ? A[(size_t)(mb + r) * lda + k] : 0.f;
    }
    {
      int k = k0 + wk;
      float4 v = make_float4(0.f,0.f,0.f,0.f);
      if (k < K) v = *reinterpret_cast<const float4*>(W + (size_t)k * N + nb + wn);
      *reinterpret_cast<float4*>(&Ws[wk][wn]) = v;
    }
    __syncthreads();
    mm16p(As, Ws, acc2, m0, n0);
    __syncthreads();
  }
#pragma unroll
  for (int p = 0; p < 2; p++)
#pragma unroll
    for (int j2 = 0; j2 < 4; j2++){
      float lo, hi; unpack2(acc2[p][j2], lo, hi);
      if (relu){ lo = fmaxf(lo, 0.f); hi = fmaxf(hi, 0.f); }
      C[(size_t)(mb + m0 + 2*p    ) * N + nb + n0 + j2] = lo;
      C[(size_t)(mb + m0 + 2*p + 1) * N + nb + n0 + j2] = hi;
    }
}

// ---------------- init unified buffers ----------------
__global__ void init_buf_kernel(const float* __restrict__ init, const float* __restrict__ x){
  int idx = blockIdx.x * 256 + threadIdx.x;    // 2*BB*ROWW
  int buf = idx / (BB * ROWW);
  int rem = idx % (BB * ROWW);
  int b = rem / ROWW, j = rem % ROWW;
  float v = 0.f;
  if (buf == 0){
    if (j < NJ3C)                          v = init[b * 85 + j];
    else if (j >= OFF_H0 && j < OFF_H0+DD) v = d_z[b][j - OFF_H0];
    else if (j >= OFF_X && j < OFF_X+INDIM)v = x[((size_t)b * FF) * INDIM + (j - OFF_X)];
    else if (j >= OFF_H1 && j < OFF_H1+DD) v = d_z[b][DD + (j - OFF_H1)];
  }
  d_buf[buf][b][j] = v;
}

__global__ void init_c_kernel(){
  int idx = blockIdx.x * 256 + threadIdx.x;    // BB*1024
  int b = idx >> 10, r = idx & 1023;
  if (r < DD) d_c0s[b][r] = d_z[b][1024 + r];
  else        d_c1s[b][r - DD] = d_z[b][1536 + (r - DD)];
}

// ---------------- LSTM epilogue: one packed row-pair -> gates -> h ----------------
__device__ __forceinline__ void lstm_pair(ull a0, ull a1, ull a2, ull a3,
                                          int b_even, int d, float (*cs)[DD],
                                          float* he, float* ho){
  float i_lo,i_hi,f_lo,f_hi,g_lo,g_hi,o_lo,o_hi;
  unpack2(a0,i_lo,i_hi); unpack2(a1,f_lo,f_hi);
  unpack2(a2,g_lo,g_hi); unpack2(a3,o_lo,o_hi);
  {
    float cn = fmaf(sigm(f_lo), cs[b_even][d], sigm(i_lo) * tanhf(g_lo));
    cs[b_even][d] = cn; *he = sigm(o_lo) * tanhf(cn);
  }
  {
    float cn = fmaf(sigm(f_hi), cs[b_even+1][d], sigm(i_hi) * tanhf(g_hi));
    cs[b_even+1][d] = cn; *ho = sigm(o_hi) * tanhf(cn);
  }
}

// ---------------- persistent recurrence kernel ----------------
__global__ __launch_bounds__(256)
void recur_kernel(const float* __restrict__ x, const float* __restrict__ decW,
                  const float* __restrict__ decB,
                  float* __restrict__ out1, float* __restrict__ out2){
  __shared__ __align__(16) float As[2][16][68];
  __shared__ __align__(16) float Ws[2][16][64];
  __shared__ __align__(16) float hs[DD];
  __shared__ float red[4][64];

  int tid = threadIdx.x, blk = blockIdx.x;
  int nb = (blk & 31) * 64, mb = (blk >> 5) * 64;
  int tx = tid & 15, ty = tid >> 4;
  int m0 = ty * 4, n0 = tx * 4;
  int r  = tid >> 2, kq = (tid & 3) * 4;
  int wk = tid >> 4, wn = (tid & 15) * 4;
  int d  = (nb + n0) >> 2;

  for (int t = 0; t < FF; t++){
    int cur = t & 1;
    const float (*bufC)[ROWW] = d_buf[cur];
    float (*bufN)[ROWW] = d_buf[cur ^ 1];

    // ---- phase A: gates0 = [pred|h0|x] @ Wpk0, K=624 ----
    {
      ull acc2[2][4];
#pragma unroll
      for (int j=0;j<4;j++){ float bv = d_cb[nb+n0+j]; PACK2(acc2[0][j],bv); acc2[1][j]=acc2[0][j]; }
      float4 av = __ldcg(reinterpret_cast<const float4*>(&bufC[mb+r][kq]));
      float4 wv = *reinterpret_cast<const float4*>(&d_Wpk0[wk][nb+wn]);
      As[0][kq+0][r]=av.x; As[0][kq+1][r]=av.y; As[0][kq+2][r]=av.z; As[0][kq+3][r]=av.w;
      *reinterpret_cast<float4*>(&Ws[0][wk][wn]) = wv;
      __syncthreads();
      for (int it = 0; it < NT_A; it++){
        int cb = it & 1;
        float4 a2, w2;
        bool more = (it+1 < NT_A);
        if (more){
          int k0 = (it+1)*16;
          a2 = __ldcg(reinterpret_cast<const float4*>(&bufC[mb+r][k0+kq]));
          w2 = *reinterpret_cast<const float4*>(&d_Wpk0[k0+wk][nb+wn]);
        }
        mm16p(As[cb], Ws[cb], acc2, m0, n0);
        if (more){
          As[cb^1][kq+0][r]=a2.x; As[cb^1][kq+1][r]=a2.y;
          As[cb^1][kq+2][r]=a2.z; As[cb^1][kq+3][r]=a2.w;
          *reinterpret_cast<float4*>(&Ws[cb^1][wk][wn]) = w2;
        }
        __syncthreads();
      }
#pragma unroll
      for (int p = 0; p < 2; p++){
        int b = mb + m0 + 2*p;
        float he, ho;
        lstm_pair(acc2[p][0], acc2[p][1], acc2[p][2], acc2[p][3], b, d, d_c0s, &he, &ho);
        bufN[b    ][OFF_H0 + d] = he;
        bufN[b + 1][OFF_H0 + d] = ho;
      }
    }
    grid_barrier();

    // ---- phase B: gates1 = [h0n|h1] @ Wpk1, K=1024 ----
    {
      ull acc2[2][4];
#pragma unroll
      for (int j=0;j<4;j++){ float bv = d_b1g[nb+n0+j]; PACK2(acc2[0][j],bv); acc2[1][j]=acc2[0][j]; }
      {
        float4 av = __ldcg(reinterpret_cast<const float4*>(&bufN[mb+r][OFF_H0 + kq]));
        float4 wv = *reinterpret_cast<const float4*>(&d_Wpk1[wk][nb+wn]);
        As[0][kq+0][r]=av.x; As[0][kq+1][r]=av.y; As[0][kq+2][r]=av.z; As[0][kq+3][r]=av.w;
        *reinterpret_cast<float4*>(&Ws[0][wk][wn]) = wv;
      }
      __syncthreads();
      for (int it = 0; it < NT_B; it++){
        int cb = it & 1;
        float4 a2, w2;
        bool more = (it+1 < NT_B);
        if (more){
          int k0 = (it+1)*16;
          const float* src = (k0 < 512) ? &bufN[mb+r][OFF_H0 + k0] : &bufC[mb+r][112 + k0];
          a2 = __ldcg(reinterpret_cast<const float4*>(src + kq));
          w2 = *reinterpret_cast<const float4*>(&d_Wpk1[k0+wk][nb+wn]);
        }
        mm16p(As[cb], Ws[cb], acc2, m0, n0);
        if (more){
          As[cb^1][kq+0][r]=a2.x; As[cb^1][kq+1][r]=a2.y;
          As[cb^1][kq+2][r]=a2.z; As[cb^1][kq+3][r]=a2.w;
          *reinterpret_cast<float4*>(&Ws[cb^1][wk][wn]) = w2;
        }
        __syncthreads();
      }
#pragma unroll
      for (int p = 0; p < 2; p++){
        int b = mb + m0 + 2*p;
        float he, ho;
        lstm_pair(acc2[p][0], acc2[p][1], acc2[p][2], acc2[p][3], b, d, d_c1s, &he, &ho);
        bufN[b    ][OFF_H1 + d] = he;
        bufN[b + 1][OFF_H1 + d] = ho;
        out2[((size_t)b       * FF + t) * 563 + d] = he;
        out2[((size_t)(b + 1) * FF + t) * 563 + d] = ho;
      }
    }
    grid_barrier();

    // ---- phase dec: pred = h1n @ dec_W + dec_b; also stage x(t+1) ----
    {
      int seg = tid >> 6, p = tid & 63;
      for (int q = 0; q < 2; q++){
        int b = blk * 2 + q;
        if (tid < 128){
          float4 hv = __ldcg(reinterpret_cast<const float4*>(&bufN[b][OFF_H1 + tid*4]));
          *reinterpret_cast<float4*>(&hs[tid*4]) = hv;
        }
        __syncthreads();
        float s = 0.f;
        if (p < NJ3C){
          int kb = seg * 128;
#pragma unroll 8
          for (int k = 0; k < 128; k++) s = fmaf(hs[kb + k], decW[(kb + k)*NJ3C + p], s);
        }
        red[seg][p] = s;
        __syncthreads();
        if (tid < 64 && p < NJ3C){
          float v = decB[p] + red[0][p] + red[1][p] + red[2][p] + red[3][p];
          bufN[b][OFF_PRED + p] = v;
          out1[((size_t)b * FF + t) * NJ3C + p] = v;
          out2[((size_t)b * FF + t) * 563 + 512 + p] = v;
        }
        __syncthreads();
      }
      if (t < FF - 1 && tid < 68){
        int q = (tid >= 34) ? 1 : 0;
        int i = tid - q * 34;
        int b = blk * 2 + q;
        bufN[b][OFF_X + i] = x[((size_t)b * FF + (t+1)) * INDIM + i];
      }
    }
    grid_barrier();
  }
}

// ---------------- launch: kernel launches ONLY ----------------
extern "C" void kernel_launch(void* const* d_in, const int* in_sizes, int n_in,
                              void* d_out, int out_size){
  const float* x     = (const float*)d_in[0];
  const float* initp = (const float*)d_in[1];
  const float* embW  = (const float*)d_in[2];
  const float* embB  = (const float*)d_in[3];
  const float* niW1  = (const float*)d_in[4];
  const float* nib1  = (const float*)d_in[5];
  const float* niW2  = (const float*)d_in[6];
  const float* nib2  = (const float*)d_in[7];
  const float* niW3  = (const float*)d_in[8];
  const float* nib3  = (const float*)d_in[9];
  const float* Wih0  = (const float*)d_in[10];
  const float* Whh0  = (const float*)d_in[11];
  const float* bih0  = (const float*)d_in[12];
  const float* bhh0  = (const float*)d_in[13];
  const float* Wih1  = (const float*)d_in[14];
  const float* Whh1  = (const float*)d_in[15];
  const float* bih1  = (const float*)d_in[16];
  const float* bhh1  = (const float*)d_in[17];
  const float* decW  = (const float*)d_in[18];
  const float* decB  = (const float*)d_in[19];

  float* out  = (float*)d_out;
  float* out1 = out;                                   // pred_kp3d [B,F,17,3]
  float* out2 = out + (size_t)BB * FF * NJ3C;          // motion_context [B,F,563]

  pack0_kernel<<<G4, 64>>>(Wih0, Whh0, embW, embB, bih0, bhh0);
  pack1_kernel<<<(KB * G4) / 256, 256>>>(Wih1, Whh1, bih1, bhh1);

  gemm_bias_act<<<dim3(DD/64,   BB/64), 256>>>(initp, 0, 85,    niW1, DD,   85,   nib1, 1, 1);
  gemm_bias_act<<<dim3(1024/64, BB/64), 256>>>(nullptr, 1, DD,  niW2, 1024, DD,   nib2, 2, 1);
  gemm_bias_act<<<dim3(G4/64,   BB/64), 256>>>(nullptr, 2, 1024, niW3, G4,  1024, nib3, 3, 0);
  init_buf_kernel<<<(2 * BB * ROWW) / 256, 256>>>(initp, x);
  init_c_kernel<<<(BB * 1024) / 256, 256>>>();

  recur_kernel<<<NBLK, 256>>>(x, decW, decB, out1, out2);
}

// round 9
// speedup vs baseline: 1.3912x; 1.3912x over previous
#include <cuda_runtime.h>
#include <math.h>
#include <stdint.h>

// Problem constants
#define BB    256
#define FF    256
#define NJ3C  51
#define INDIM 34
#define DD    512
#define G4    2048
#define ROWW  1152          // unified state row stride (floats)
#define OFF_PRED 0          // [0,51)  pred, [51,64) zero pad
#define OFF_H0   64         // [64,576) h0
#define OFF_X    576        // [576,610) x, [610,624) zero pad
#define OFF_H1   624        // [624,1136) h1, rest pad
#define KA_PAD   624        // phase A K (incl zero pads)
#define NT_A     39         // 624/16
#define KB       1024
#define NT_B     64
#define TM       32         // m-tile rows
#define NBLK     256        // 2 blocks/SM co-resident

typedef unsigned long long ull;

// ---------------- device scratch (static, no allocation) ----------------
__device__ __align__(16) float d_buf[2][BB][ROWW];   // unified state, double buffered
__device__ __align__(16) float d_c0s[BB][DD];
__device__ __align__(16) float d_c1s[BB][DD];
__device__ __align__(16) float d_Wpk0[KA_PAD][G4];   // packed LSTM0 W, k-major, n=d*4+gate
__device__ float d_cb[G4];                           // folded bias LSTM0
__device__ __align__(16) float d_Wpk1[KB][G4];       // packed LSTM1 W
__device__ float d_b1g[G4];                          // bias LSTM1
__device__ __align__(16) float d_t1[BB][DD];
__device__ __align__(16) float d_t2[BB][1024];
__device__ __align__(16) float d_z[BB][G4];
__device__ unsigned d_bar_count;
__device__ volatile unsigned d_bar_gen;

__device__ __forceinline__ float sigm(float x){ return 1.0f/(1.0f+expf(-x)); }

// ---------------- packed f32x2 helpers (FFMA2 path) ----------------
#define PACK2(d, x) asm("mov.b64 %0, {%1, %1};" : "=l"(d) : "r"(__float_as_uint(x)))
#define FMA2(d, a, b) asm("fma.rn.f32x2 %0, %1, %2, %0;" : "+l"(d) : "l"(a), "l"(b))
__device__ __forceinline__ void unpack2(ull v, float& lo, float& hi){
  unsigned ulo, uhi;
  asm("mov.b64 {%0, %1}, %2;" : "=r"(ulo), "=r"(uhi) : "l"(v));
  lo = __uint_as_float(ulo); hi = __uint_as_float(uhi);
}

// ---------------- grid barrier (256 co-resident blocks) ----------------
__device__ __forceinline__ void grid_barrier(){
  __syncthreads();
  if (threadIdx.x == 0){
    unsigned gen = d_bar_gen;
    __threadfence();
    if (atomicAdd(&d_bar_count, 1u) == NBLK - 1){
      d_bar_count = 0;
      __threadfence();
      d_bar_gen = gen + 1;
    } else {
      while (d_bar_gen == gen) { __nanosleep(32); }
      __threadfence();
    }
  }
  __syncthreads();
}

// ---------------- 16-deep packed-FMA core: 2x4 microtile ----------------
// acc2[j]: rows (m0, m0+1) packed, column n0+j
__device__ __forceinline__ void mm16p2(const float (*As)[36], const float (*Ws)[64],
                                       ull acc2[4], int m0, int n0){
#pragma unroll
  for (int kk = 0; kk < 16; kk++){
    ull aa = *reinterpret_cast<const ull*>(&As[kk][m0]);
    float4 b4 = *reinterpret_cast<const float4*>(&Ws[kk][n0]);
    ull b0, b1, b2, b3;
    PACK2(b0, b4.x); PACK2(b1, b4.y); PACK2(b2, b4.z); PACK2(b3, b4.w);
    FMA2(acc2[0], aa, b0); FMA2(acc2[1], aa, b1);
    FMA2(acc2[2], aa, b2); FMA2(acc2[3], aa, b3);
  }
}

// ---------------- 4x4 core for init MLP GEMM ----------------
__device__ __forceinline__ void mm16p4(const float (*As)[68], const float (*Ws)[64],
                                       ull acc2[2][4], int m0, int n0){
#pragma unroll
  for (int kk = 0; kk < 16; kk++){
    ulonglong2 aa = *reinterpret_cast<const ulonglong2*>(&As[kk][m0]);
    float4 b4 = *reinterpret_cast<const float4*>(&Ws[kk][n0]);
    ull b0, b1, b2, b3;
    PACK2(b0, b4.x); PACK2(b1, b4.y); PACK2(b2, b4.z); PACK2(b3, b4.w);
    FMA2(acc2[0][0], aa.x, b0); FMA2(acc2[0][1], aa.x, b1);
    FMA2(acc2[0][2], aa.x, b2); FMA2(acc2[0][3], aa.x, b3);
    FMA2(acc2[1][0], aa.y, b0); FMA2(acc2[1][1], aa.y, b1);
    FMA2(acc2[1][2], aa.y, b2); FMA2(acc2[1][3], aa.y, b3);
  }
}

// ---------------- pack ALL weights (merged: LSTM0 fold + LSTM1) ----------------
// n = d*4 + g maps to reference gate row j = g*512 + d
// Wpk0 k map: [0,51) Wih0 pred cols; [51,64) 0; [64,576) Whh0; [576,610) embed fold; [610,624) 0
__global__ void pack_all_kernel(const float* __restrict__ Wih0, const float* __restrict__ Whh0,
                                const float* __restrict__ embW, const float* __restrict__ embB,
                                const float* __restrict__ bih0, const float* __restrict__ bhh0,
                                const float* __restrict__ Wih1, const float* __restrict__ Whh1,
                                const float* __restrict__ bih1, const float* __restrict__ bhh1){
  int n = blockIdx.x;
  int j = (n & 3) * DD + (n >> 2);
  __shared__ float row[DD];
  for (int k = threadIdx.x; k < DD; k += 64) row[k] = Wih0[j*563 + k];
  __syncthreads();
  for (int k = threadIdx.x; k < KA_PAD; k += 64){
    float w;
    if (k < NJ3C)       w = Wih0[j*563 + DD + k];
    else if (k < 64)    w = 0.f;
    else if (k < 576)   w = Whh0[j*DD + (k - 64)];
    else if (k < 610){
      const float* er = embW + (k - 576)*DD;
      float s = 0.f;
      for (int kk = 0; kk < DD; kk++) s = fmaf(er[kk], row[kk], s);
      w = s;
    } else w = 0.f;
    d_Wpk0[k][n] = w;
  }
  for (int k = threadIdx.x; k < KB; k += 64)
    d_Wpk1[k][n] = (k < DD) ? Wih1[j*DD + k] : Whh1[j*DD + (k - DD)];
  if (threadIdx.x == 0){
    float s = 0.f;
    for (int kk = 0; kk < DD; kk++) s = fmaf(embB[kk], row[kk], s);
    d_cb[n]  = s + bih0[j] + bhh0[j];
    d_b1g[n] = bih1[j] + bhh1[j];
  }
}

// ---------------- init-MLP GEMM (one-shot, 64x64 tiles) ----------------
__global__ __launch_bounds__(256)
void gemm_bias_act(const float* __restrict__ Aext, int a_sel, int lda,
                   const float* __restrict__ W, int N, int K,
                   const float* __restrict__ bias, int c_sel, int relu){
  const float* A = (a_sel == 0) ? Aext : (a_sel == 1 ? &d_t1[0][0] : &d_t2[0][0]);
  float* C = (c_sel == 1) ? &d_t1[0][0] : (c_sel == 2 ? &d_t2[0][0] : &d_z[0][0]);
  __shared__ __align__(16) float As[16][68];
  __shared__ __align__(16) float Ws[16][64];
  int tid = threadIdx.x;
  int tx = tid & 15, ty = tid >> 4;
  int nb = blockIdx.x * 64, mb = blockIdx.y * 64;
  int m0 = ty * 4, n0 = tx * 4;
  ull acc2[2][4];
#pragma unroll
  for (int j2 = 0; j2 < 4; j2++){
    float bv = bias[nb + n0 + j2];
    PACK2(acc2[0][j2], bv);
    acc2[1][j2] = acc2[0][j2];
  }
  int r  = tid >> 2, kq = (tid & 3) * 4;
  int wk = tid >> 4, wn = (tid & 15) * 4;
  for (int k0 = 0; k0 < K; k0 += 16){
#pragma unroll
    for (int i = 0; i < 4; i++){
      int k = k0 + kq + i;
      As[kq+i][r] = (k < K) ? A[(size_t)(mb + r) * lda + k] : 0.f;
    }
    {
      int k = k0 + wk;
      float4 v = make_float4(0.f,0.f,0.f,0.f);
      if (k < K) v = *reinterpret_cast<const float4*>(W + (size_t)k * N + nb + wn);
      *reinterpret_cast<float4*>(&Ws[wk][wn]) = v;
    }
    __syncthreads();
    mm16p4(As, Ws, acc2, m0, n0);
    __syncthreads();
  }
#pragma unroll
  for (int p = 0; p < 2; p++)
#pragma unroll
    for (int j2 = 0; j2 < 4; j2++){
      float lo, hi; unpack2(acc2[p][j2], lo, hi);
      if (relu){ lo = fmaxf(lo, 0.f); hi = fmaxf(hi, 0.f); }
      C[(size_t)(mb + m0 + 2*p    ) * N + nb + n0 + j2] = lo;
      C[(size_t)(mb + m0 + 2*p + 1) * N + nb + n0 + j2] = hi;
    }
}

// ---------------- init unified buffers + c state (merged) ----------------
__global__ void init_all_kernel(const float* __restrict__ init, const float* __restrict__ x){
  int idx = blockIdx.x * 256 + threadIdx.x;
  const int NBUF = 2 * BB * ROWW;
  if (idx < NBUF){
    int buf = idx / (BB * ROWW);
    int rem = idx % (BB * ROWW);
    int b = rem / ROWW, j = rem % ROWW;
    float v = 0.f;
    if (buf == 0){
      if (j < NJ3C)                           v = init[b * 85 + j];
      else if (j >= OFF_H0 && j < OFF_H0+DD)  v = d_z[b][j - OFF_H0];
      else if (j >= OFF_X && j < OFF_X+INDIM) v = x[((size_t)b * FF) * INDIM + (j - OFF_X)];
      else if (j >= OFF_H1 && j < OFF_H1+DD)  v = d_z[b][DD + (j - OFF_H1)];
    }
    d_buf[buf][b][j] = v;
  } else {
    int idx2 = idx - NBUF;               // BB*1024
    if (idx2 < BB * 1024){
      int b = idx2 >> 10, r = idx2 & 1023;
      if (r < DD) d_c0s[b][r] = d_z[b][1024 + r];
      else        d_c1s[b][r - DD] = d_z[b][1536 + (r - DD)];
    }
  }
}

// ---------------- LSTM epilogue: one packed row-pair -> gates -> h ----------------
__device__ __forceinline__ void lstm_pair(ull a0, ull a1, ull a2, ull a3,
                                          int b_even, int d, float (*cs)[DD],
                                          float* he, float* ho){
  float i_lo,i_hi,f_lo,f_hi,g_lo,g_hi,o_lo,o_hi;
  unpack2(a0,i_lo,i_hi); unpack2(a1,f_lo,f_hi);
  unpack2(a2,g_lo,g_hi); unpack2(a3,o_lo,o_hi);
  {
    float cn = fmaf(sigm(f_lo), cs[b_even][d], sigm(i_lo) * tanhf(g_lo));
    cs[b_even][d] = cn; *he = sigm(o_lo) * tanhf(cn);
  }
  {
    float cn = fmaf(sigm(f_hi), cs[b_even+1][d], sigm(i_hi) * tanhf(g_hi));
    cs[b_even+1][d] = cn; *ho = sigm(o_hi) * tanhf(cn);
  }
}

// ---------------- persistent recurrence kernel: 256 blocks, 2/SM ----------------
__global__ __launch_bounds__(256, 2)
void recur_kernel(const float* __restrict__ x, const float* __restrict__ decW,
                  const float* __restrict__ decB,
                  float* __restrict__ out1, float* __restrict__ out2){
  __shared__ __align__(16) float As[2][16][36];
  __shared__ __align__(16) float Ws[2][16][64];
  __shared__ __align__(16) float hs[DD];
  __shared__ float red[4][64];

  int tid = threadIdx.x, blk = blockIdx.x;
  int nb = (blk & 31) * 64;          // 32 n-tiles
  int mb = (blk >> 5) * TM;          // 8 m-tiles of 32
  int tx = tid & 15, ty = tid >> 4;
  int m0 = ty * 2, n0 = tx * 4;
  int r  = tid >> 3, kq = (tid & 7) * 2;   // A loader: 32 rows x 8 k-pairs
  int wk = tid >> 4, wn = (tid & 15) * 4;  // W loader
  int d  = (nb + n0) >> 2;

  for (int t = 0; t < FF; t++){
    int cur = t & 1;
    const float (*bufC)[ROWW] = d_buf[cur];
    float (*bufN)[ROWW] = d_buf[cur ^ 1];

    // ---- phase A: gates0 = [pred|h0|x] @ Wpk0, K=624 ----
    {
      ull acc2[4];
#pragma unroll
      for (int j = 0; j < 4; j++) PACK2(acc2[j], d_cb[nb+n0+j]);
      float2 av = __ldcg(reinterpret_cast<const float2*>(&bufC[mb+r][kq]));
      float4 wv = *reinterpret_cast<const float4*>(&d_Wpk0[wk][nb+wn]);
      As[0][kq][r] = av.x; As[0][kq+1][r] = av.y;
      *reinterpret_cast<float4*>(&Ws[0][wk][wn]) = wv;
      __syncthreads();
      for (int it = 0; it < NT_A; it++){
        int cb = it & 1;
        bool more = (it + 1 < NT_A);
        if (more){
          int k0 = (it + 1) * 16;
          av = __ldcg(reinterpret_cast<const float2*>(&bufC[mb+r][k0+kq]));
          wv = *reinterpret_cast<const float4*>(&d_Wpk0[k0+wk][nb+wn]);
        }
        mm16p2(As[cb], Ws[cb], acc2, m0, n0);
        if (more){
          As[cb^1][kq][r] = av.x; As[cb^1][kq+1][r] = av.y;
          *reinterpret_cast<float4*>(&Ws[cb^1][wk][wn]) = wv;
        }
        __syncthreads();
      }
      int b = mb + m0;
      float he, ho;
      lstm_pair(acc2[0], acc2[1], acc2[2], acc2[3], b, d, d_c0s, &he, &ho);
      bufN[b    ][OFF_H0 + d] = he;
      bufN[b + 1][OFF_H0 + d] = ho;
    }
    grid_barrier();

    // ---- phase B: gates1 = [h0n|h1] @ Wpk1, K=1024 ----
    {
      ull acc2[4];
#pragma unroll
      for (int j = 0; j < 4; j++) PACK2(acc2[j], d_b1g[nb+n0+j]);
      float2 av = __ldcg(reinterpret_cast<const float2*>(&bufN[mb+r][OFF_H0 + kq]));
      float4 wv = *reinterpret_cast<const float4*>(&d_Wpk1[wk][nb+wn]);
      As[0][kq][r] = av.x; As[0][kq+1][r] = av.y;
      *reinterpret_cast<float4*>(&Ws[0][wk][wn]) = wv;
      __syncthreads();
      for (int it = 0; it < NT_B; it++){
        int cb = it & 1;
        bool more = (it + 1 < NT_B);
        if (more){
          int k0 = (it + 1) * 16;
          const float* src = (k0 < 512) ? &bufN[mb+r][OFF_H0 + k0] : &bufC[mb+r][112 + k0];
          av = __ldcg(reinterpret_cast<const float2*>(src + kq));
          wv = *reinterpret_cast<const float4*>(&d_Wpk1[k0+wk][nb+wn]);
        }
        mm16p2(As[cb], Ws[cb], acc2, m0, n0);
        if (more){
          As[cb^1][kq][r] = av.x; As[cb^1][kq+1][r] = av.y;
          *reinterpret_cast<float4*>(&Ws[cb^1][wk][wn]) = wv;
        }
        __syncthreads();
      }
      int b = mb + m0;
      float he, ho;
      lstm_pair(acc2[0], acc2[1], acc2[2], acc2[3], b, d, d_c1s, &he, &ho);
      bufN[b    ][OFF_H1 + d] = he;
      bufN[b + 1][OFF_H1 + d] = ho;
      out2[((size_t)b       * FF + t) * 563 + d] = he;
      out2[((size_t)(b + 1) * FF + t) * 563 + d] = ho;
    }
    grid_barrier();

    // ---- phase dec: pred(b=blk) = h1n @ dec_W + dec_b; stage x(t+1) ----
    {
      int b = blk;                          // 256 blocks = 256 batches
      if (tid < 128){
        float4 hv = __ldcg(reinterpret_cast<const float4*>(&bufN[b][OFF_H1 + tid*4]));
        *reinterpret_cast<float4*>(&hs[tid*4]) = hv;
      }
      __syncthreads();
      int seg = tid >> 6, p = tid & 63;
      float s = 0.f;
      if (p < NJ3C){
        int kb = seg * 128;
#pragma unroll 8
        for (int k = 0; k < 128; k++) s = fmaf(hs[kb + k], decW[(kb + k)*NJ3C + p], s);
      }
      red[seg][p] = s;
      __syncthreads();
      if (tid < 64 && p < NJ3C){
        float v = decB[p] + red[0][p] + red[1][p] + red[2][p] + red[3][p];
        bufN[b][OFF_PRED + p] = v;
        out1[((size_t)b * FF + t) * NJ3C + p] = v;
        out2[((size_t)b * FF + t) * 563 + 512 + p] = v;
      }
      if (t < FF - 1 && tid < INDIM)
        bufN[b][OFF_X + tid] = x[((size_t)b * FF + (t+1)) * INDIM + tid];
    }
    grid_barrier();
  }
}

// ---------------- launch: kernel launches ONLY (recur = launch index 5 for ncu) ----------------
extern "C" void kernel_launch(void* const* d_in, const int* in_sizes, int n_in,
                              void* d_out, int out_size){
  const float* x     = (const float*)d_in[0];
  const float* initp = (const float*)d_in[1];
  const float* embW  = (const float*)d_in[2];
  const float* embB  = (const float*)d_in[3];
  const float* niW1  = (const float*)d_in[4];
  const float* nib1  = (const float*)d_in[5];
  const float* niW2  = (const float*)d_in[6];
  const float* nib2  = (const float*)d_in[7];
  const float* niW3  = (const float*)d_in[8];
  const float* nib3  = (const float*)d_in[9];
  const float* Wih0  = (const float*)d_in[10];
  const float* Whh0  = (const float*)d_in[11];
  const float* bih0  = (const float*)d_in[12];
  const float* bhh0  = (const float*)d_in[13];
  const float* Wih1  = (const float*)d_in[14];
  const float* Whh1  = (const float*)d_in[15];
  const float* bih1  = (const float*)d_in[16];
  const float* bhh1  = (const float*)d_in[17];
  const float* decW  = (const float*)d_in[18];
  const float* decB  = (const float*)d_in[19];

  float* out  = (float*)d_out;
  float* out1 = out;                                   // pred_kp3d [B,F,17,3]
  float* out2 = out + (size_t)BB * FF * NJ3C;          // motion_context [B,F,563]

  // 0: pack all weights
  pack_all_kernel<<<G4, 64>>>(Wih0, Whh0, embW, embB, bih0, bhh0,
                              Wih1, Whh1, bih1, bhh1);
  // 1-3: init MLP  85 -> 512 -> 1024 -> 2048
  gemm_bias_act<<<dim3(DD/64,   BB/64), 256>>>(initp, 0, 85,     niW1, DD,   85,   nib1, 1, 1);
  gemm_bias_act<<<dim3(1024/64, BB/64), 256>>>(nullptr, 1, DD,   niW2, 1024, DD,   nib2, 2, 1);
  gemm_bias_act<<<dim3(G4/64,   BB/64), 256>>>(nullptr, 2, 1024, niW3, G4,  1024,  nib3, 3, 0);
  // 4: scatter into state buffers
  init_all_kernel<<<(2*BB*ROWW + BB*1024) / 256, 256>>>(initp, x);
  // 5: persistent recurrence (profiled by ncu -s 5)
  recur_kernel<<<NBLK, 256>>>(x, decW, decB, out1, out2);
}